// round 2
// baseline (speedup 1.0000x reference)
#include <cuda_runtime.h>

#define BATCH 512
#define DD 256

// ---- device scratch (no allocations allowed) ----
__device__ float g_rs[BATCH * DD];
__device__ float g_cs[BATCH * DD];
__device__ float g_vrow[BATCH * DD];
__device__ float g_vcol[BATCH * DD];
__device__ float g_table[12 * 9 * 2];   // [seg 0..10, sentinel 11][tap 0..8][A,B]
__device__ float g_th[10];              // sorted breakpoints
__device__ float g_fcacc[4];

// ---------------------------------------------------------------------------
// Setup: build piecewise-linear table of G_tap(t) = sum_c w2[c,tap]*relu(w1_c*t+b1_c)
// Segment k covers [th[k-1], th[k]); sentinel segment 11 is all-zero.
// ---------------------------------------------------------------------------
__global__ void k_setup(const float* __restrict__ w1, const float* __restrict__ b1,
                        const float* __restrict__ w2) {
    int tid = threadIdx.x;
    float w1l[10], b1l[10], th[10];
#pragma unroll
    for (int c = 0; c < 10; c++) { w1l[c] = w1[c]; b1l[c] = b1[c]; }
#pragma unroll
    for (int c = 0; c < 10; c++)
        th[c] = (fabsf(w1l[c]) > 1e-30f) ? (-b1l[c] / w1l[c]) : 3e30f;
    // insertion sort (redundant per-thread, tiny)
    for (int a = 1; a < 10; a++) {
        float key = th[a]; int j = a - 1;
        while (j >= 0 && th[j] > key) { th[j + 1] = th[j]; j--; }
        th[j + 1] = key;
    }
    if (tid < 10) g_th[tid] = th[tid];
    if (tid < 108) {                    // 12 segments x 9 taps
        int k = tid / 9, tap = tid % 9;
        float A = 0.f, Bv = 0.f;
        if (k < 11) {
            float lo = (k == 0)  ? -1e8f : fmaxf(th[k - 1], -1e8f);
            float hi = (k == 10) ?  1e8f : fminf(th[k],  1e8f);
            float tm = 0.5f * (lo + hi);     // test point inside segment
            for (int c = 0; c < 10; c++) {
                if (w1l[c] * tm + b1l[c] > 0.f) {   // channel active on this segment
                    float wt = w2[c * 9 + tap];
                    A  += w1l[c] * wt;
                    Bv += b1l[c] * wt;
                }
            }
        }
        g_table[tid * 2 + 0] = A;
        g_table[tid * 2 + 1] = Bv;
    }
    if (tid >= 112 && tid < 116) g_fcacc[tid - 112] = 0.f;
}

// ---------------------------------------------------------------------------
// Pass 1: rs[b,i] = sum_j x ; cs[b,j] = sum_i x. Also zeroes vcol.
// One block per image; thread = column; coalesced streaming of 134 MB.
// ---------------------------------------------------------------------------
__global__ void __launch_bounds__(256) k_pass1(const float* __restrict__ x) {
    __shared__ float s_part[8 * DD];
    int b = blockIdx.x, tid = threadIdx.x;
    int w = tid >> 5, lane = tid & 31;
    const float* xb = x + (size_t)b * (DD * DD);
    float cs = 0.f;
#pragma unroll 4
    for (int i = 0; i < DD; i++) {
        float v = xb[i * DD + tid];
        cs += v;
        float s = v;
#pragma unroll
        for (int o = 16; o; o >>= 1) s += __shfl_xor_sync(0xffffffffu, s, o);
        if (lane == 0) s_part[w * DD + i] = s;
    }
    __syncthreads();
    float rs = 0.f;
#pragma unroll
    for (int ww = 0; ww < 8; ww++) rs += s_part[ww * DD + tid];
    g_rs[b * DD + tid]   = rs;
    g_cs[b * DD + tid]   = cs;
    g_vcol[b * DD + tid] = 0.f;
}

// ---------------------------------------------------------------------------
// Pass 2: y over the active band (j <= i+2), accumulating row sums (regs) and
// column sums (butterfly + 1 global atomic per warp-step).
// Warp lanes own rows; each lane handles rows i and 255-i (balanced warps).
// Sliding 3-column window of (t, tablePtr) state; 9 LDS.64 + 18 FMA per pixel.
// ---------------------------------------------------------------------------
__global__ void __launch_bounds__(64) k_pass2(const float* __restrict__ b2) {
    __shared__ float2 s_tab[108];
    __shared__ float  s_cs[DD];
    int b = blockIdx.y;
    int tid = threadIdx.x, warp = tid >> 5, lane = tid & 31;
    int s = blockIdx.x * 2 + warp;          // row-strip 0..3 (mirror covers 4..7)

    for (int idx = tid; idx < 108; idx += 64)
        s_tab[idx] = make_float2(g_table[idx * 2], g_table[idx * 2 + 1]);
    for (int idx = tid; idx < DD; idx += 64)
        s_cs[idx] = g_cs[b * DD + idx];
    float th[10];
#pragma unroll
    for (int k = 0; k < 10; k++) th[k] = g_th[k];
    float b2v = b2[0];
    __syncthreads();

    const float2* tab  = s_tab;
    const float2* SENT = tab + 11 * 9;      // all-zero sentinel row
    int ib = b * DD;

    for (int half = 0; half < 2; half++) {
        int i = (half == 0) ? (s * 32 + lane) : (255 - (s * 32 + lane));
        float rs0 = g_rs[ib + i];
        float rsm = (i > 0)   ? g_rs[ib + i - 1] : 0.f;
        float rsp = (i < 255) ? g_rs[ib + i + 1] : 0.f;
        bool rvm = (i > 0), rvp = (i < 255);
        int jmaxl = min(i + 2, 255);
        int jmaxw = __reduce_max_sync(0xffffffffu, jmaxl);

        auto segof = [&](float t) -> int {
            bool mid = (t >= th[0]) && (t < th[9]);
            int sg;
            if (__any_sync(0xffffffffu, mid)) {
                sg = 0;
#pragma unroll
                for (int k = 0; k < 10; k++) sg += (t >= th[k]) ? 1 : 0;
            } else {
                sg = (t >= th[9]) ? 10 : 0;
            }
            return sg;
        };
        auto colcell = [&](int jc, float& tA, float& tB, float& tC,
                           const float2*& pA, const float2*& pB, const float2*& pC) {
            bool jok = (unsigned)jc < 256u;
            float c = s_cs[jok ? jc : 0];
            tA = rsm + c; tB = rs0 + c; tC = rsp + c;
            bool vA = jok && rvm && (i - 1 >= jc);
            bool vB = jok &&        (i     >= jc);
            bool vC = jok && rvp && (i + 1 >= jc);
            int sA = segof(tA), sB = segof(tB), sC = segof(tC);
            pA = vA ? (tab + sA * 9) : SENT;
            pB = vB ? (tab + sB * 9) : SENT;
            pC = vC ? (tab + sC * 9) : SENT;
        };

        float t00, t01, t02, t10, t11, t12, t20, t21, t22;
        const float2 *p00, *p01, *p02, *p10, *p11, *p12, *p20, *p21, *p22;
        t00 = t10 = t20 = 0.f; p00 = p10 = p20 = SENT;          // column j-1 = -1
        colcell(0, t01, t11, t21, p01, p11, p21);                // column j
        colcell(1, t02, t12, t22, p02, p12, p22);                // column j+1

        float vracc = 0.f;
        for (int j = 0; j <= jmaxw; j++) {
            float aA = 0.f, aB = 0.f; float2 ab;
            ab = p00[0]; aA = fmaf(ab.x, t00, aA); aB += ab.y;
            ab = p01[1]; aA = fmaf(ab.x, t01, aA); aB += ab.y;
            ab = p02[2]; aA = fmaf(ab.x, t02, aA); aB += ab.y;
            ab = p10[3]; aA = fmaf(ab.x, t10, aA); aB += ab.y;
            ab = p11[4]; aA = fmaf(ab.x, t11, aA); aB += ab.y;
            ab = p12[5]; aA = fmaf(ab.x, t12, aA); aB += ab.y;
            ab = p20[6]; aA = fmaf(ab.x, t20, aA); aB += ab.y;
            ab = p21[7]; aA = fmaf(ab.x, t21, aA); aB += ab.y;
            ab = p22[8]; aA = fmaf(ab.x, t22, aA); aB += ab.y;
            float y  = fmaxf(aA + aB + b2v, 0.f);
            float yv = (j <= jmaxl) ? y : 0.f;
            vracc += yv;
            float csum = yv;
#pragma unroll
            for (int o = 16; o; o >>= 1) csum += __shfl_xor_sync(0xffffffffu, csum, o);
            if (lane == 0) atomicAdd(&g_vcol[ib + j], csum);
            // slide window
            t00 = t01; t01 = t02; t10 = t11; t11 = t12; t20 = t21; t21 = t22;
            p00 = p01; p01 = p02; p10 = p11; p11 = p12; p20 = p21; p21 = p22;
            colcell(j + 2, t02, t12, t22, p02, p12, p22);
        }
        g_vrow[ib + i] = vracc;
    }
}

// ---------------------------------------------------------------------------
// Pass 3: v[b,i] = vrow + vcol + analytic constant region; fused fc1 partials.
// ---------------------------------------------------------------------------
__global__ void __launch_bounds__(256) k_pass3(const float* __restrict__ fc1_w,
                                               const float* __restrict__ b2) {
    __shared__ float s_red[8][4];
    int b = blockIdx.x, i = threadIdx.x;
    int g = b * DD + i;
    float y0  = fmaxf(b2[0], 0.f);
    float cnt = (float)(max(0, 253 - i) + max(0, i - 2));
    float v = g_vrow[g] + g_vcol[g] + y0 * cnt;
    const int S = BATCH * DD;
    float p0 = fc1_w[g]         * v;
    float p1 = fc1_w[S + g]     * v;
    float p2 = fc1_w[2 * S + g] * v;
    float p3 = fc1_w[3 * S + g] * v;
#pragma unroll
    for (int o = 16; o; o >>= 1) {
        p0 += __shfl_xor_sync(0xffffffffu, p0, o);
        p1 += __shfl_xor_sync(0xffffffffu, p1, o);
        p2 += __shfl_xor_sync(0xffffffffu, p2, o);
        p3 += __shfl_xor_sync(0xffffffffu, p3, o);
    }
    int w = i >> 5, lane = i & 31;
    if (lane == 0) { s_red[w][0] = p0; s_red[w][1] = p1; s_red[w][2] = p2; s_red[w][3] = p3; }
    __syncthreads();
    if (i < 4) {
        float acc = 0.f;
#pragma unroll
        for (int ww = 0; ww < 8; ww++) acc += s_red[ww][i];
        atomicAdd(&g_fcacc[i], acc);
    }
}

// ---------------------------------------------------------------------------
// Pass 4: fc2
// ---------------------------------------------------------------------------
__global__ void k_pass4(const float* __restrict__ fc1_b, const float* __restrict__ fc2_w,
                        const float* __restrict__ fc2_b, float* __restrict__ out) {
    int o = threadIdx.x;
    if (o < 2) {
        float r = fc2_b[o];
#pragma unroll
        for (int k = 0; k < 4; k++) {
            float h = fmaxf(g_fcacc[k] + fc1_b[k], 0.f);
            r = fmaf(fc2_w[o * 4 + k], h, r);
        }
        out[o] = r;
    }
}

extern "C" void kernel_launch(void* const* d_in, const int* in_sizes, int n_in,
                              void* d_out, int out_size) {
    const float* x    = (const float*)d_in[0];
    const float* w1   = (const float*)d_in[1];
    const float* b1   = (const float*)d_in[2];
    const float* w2   = (const float*)d_in[3];
    const float* b2   = (const float*)d_in[4];
    const float* fc1w = (const float*)d_in[5];
    const float* fc1b = (const float*)d_in[6];
    const float* fc2w = (const float*)d_in[7];
    const float* fc2b = (const float*)d_in[8];
    (void)in_sizes; (void)n_in; (void)out_size;

    k_setup<<<1, 128>>>(w1, b1, w2);
    k_pass1<<<BATCH, 256>>>(x);
    k_pass2<<<dim3(2, BATCH), 64>>>(b2);
    k_pass3<<<BATCH, 256>>>(fc1w, b2);
    k_pass4<<<1, 32>>>(fc1b, fc2w, fc2b, (float*)d_out);
}